// round 15
// baseline (speedup 1.0000x reference)
#include <cuda_runtime.h>
#include <math.h>

// Problem constants
#define Bc   2
#define Sc   2048
#define HIDc 2048
#define Hc   16
#define HKVc 4
#define Dc   128

// ---------------------------------------------------------------------------
// Scratch (device globals; no dynamic allocation allowed)
// ---------------------------------------------------------------------------
__device__ float g_q [(size_t)Bc * Sc * Hc   * Dc];   // [B,S,H*D]   raw Q proj
__device__ float g_k [(size_t)Bc * Sc * HKVc * Dc];   // [B,S,HKV*D] raw K proj
__device__ float g_v [(size_t)Bc * Sc * HKVc * Dc];   // [B,S,HKV*D] raw V proj
__device__ float g_qt[(size_t)Bc * Sc * Hc   * Dc];   // [B,H,S,D]   rope+rms Q
__device__ float g_kt[(size_t)Bc * Sc * HKVc * Dc];   // [B,HKV,S,D] rope+rms K
__device__ float g_vt[(size_t)Bc * Sc * HKVc * Dc];   // [B,HKV,S,D] V transposed
__device__ float g_ao[(size_t)Bc * Sc * Hc   * Dc];   // [B,S,H*D]   attn output

// ---------------------------------------------------------------------------
// SGEMM: C[M,N] = A[M,K] @ W[N,K]^T   (all row-major, dims multiples of 128/8)
// 128x128 block tile, 8-deep K, 8x8 per thread, 256 threads.
// ---------------------------------------------------------------------------
__global__ __launch_bounds__(256)
void sgemm_nt(const float* __restrict__ A, const float* __restrict__ W,
              float* __restrict__ C, int M, int N, int K) {
    __shared__ float As[8][128];
    __shared__ float Bs[8][128];

    const int tid = threadIdx.x;
    const int m0  = blockIdx.y * 128;
    const int n0  = blockIdx.x * 128;
    const int tx  = tid & 15;         // 0..15 -> 8 output cols each
    const int ty  = tid >> 4;         // 0..15 -> 8 output rows each
    const int lrow = tid >> 1;        // 0..127 (load row within tile)
    const int lcol = (tid & 1) << 2;  // 0 or 4  (load col within K-slab)

    const float* Ap = A + (size_t)(m0 + lrow) * K + lcol;
    const float* Wp = W + (size_t)(n0 + lrow) * K + lcol;

    float acc[8][8];
#pragma unroll
    for (int i = 0; i < 8; i++)
#pragma unroll
        for (int j = 0; j < 8; j++) acc[i][j] = 0.0f;

    for (int k0 = 0; k0 < K; k0 += 8) {
        float4 av = *(const float4*)(Ap + k0);
        float4 wv = *(const float4*)(Wp + k0);
        __syncthreads();
        As[lcol + 0][lrow] = av.x;
        As[lcol + 1][lrow] = av.y;
        As[lcol + 2][lrow] = av.z;
        As[lcol + 3][lrow] = av.w;
        Bs[lcol + 0][lrow] = wv.x;
        Bs[lcol + 1][lrow] = wv.y;
        Bs[lcol + 2][lrow] = wv.z;
        Bs[lcol + 3][lrow] = wv.w;
        __syncthreads();
#pragma unroll
        for (int kk = 0; kk < 8; kk++) {
            float a[8], b[8];
            *(float4*)&a[0] = *(const float4*)&As[kk][ty * 8];
            *(float4*)&a[4] = *(const float4*)&As[kk][ty * 8 + 4];
            *(float4*)&b[0] = *(const float4*)&Bs[kk][tx * 8];
            *(float4*)&b[4] = *(const float4*)&Bs[kk][tx * 8 + 4];
#pragma unroll
            for (int i = 0; i < 8; i++)
#pragma unroll
                for (int j = 0; j < 8; j++)
                    acc[i][j] += a[i] * b[j];
        }
    }

#pragma unroll
    for (int i = 0; i < 8; i++) {
        float* Cp = C + (size_t)(m0 + ty * 8 + i) * N + n0 + tx * 8;
        float4 c0 = make_float4(acc[i][0], acc[i][1], acc[i][2], acc[i][3]);
        float4 c1 = make_float4(acc[i][4], acc[i][5], acc[i][6], acc[i][7]);
        *(float4*)Cp       = c0;
        *(float4*)(Cp + 4) = c1;
    }
}

// ---------------------------------------------------------------------------
// RoPE + RMSNorm + transpose: src [B,S,nh*D] -> dst [B,nh,S,D]
// One block (128 threads) per (b,s,h). apply=0 -> plain transpose (for V).
// ---------------------------------------------------------------------------
__global__ __launch_bounds__(128)
void rope_rms_transpose(const float* __restrict__ src, float* __restrict__ dst,
                        const float* __restrict__ cosp, const float* __restrict__ sinp,
                        int nh, int apply) {
    const int idx = blockIdx.x;
    const int h = idx % nh;
    const int s = (idx / nh) % Sc;
    const int b = idx / (nh * Sc);
    const int d = threadIdx.x;

    float val = src[((size_t)(b * Sc + s) * nh + h) * Dc + d];
    float y = val;

    if (apply) {
        __shared__ float buf[Dc];
        __shared__ float wsum[4];
        buf[d] = val;
        __syncthreads();
        if (d < 64) {
            float c  = cosp[s * 64 + d];
            float sn = sinp[s * 64 + d];
            y = buf[d] * c + buf[d + 64] * sn;
        } else {
            float c  = cosp[s * 64 + d - 64];
            float sn = sinp[s * 64 + d - 64];
            y = -buf[d - 64] * sn + buf[d] * c;
        }
        float sq = y * y;
#pragma unroll
        for (int off = 16; off; off >>= 1)
            sq += __shfl_xor_sync(0xffffffffu, sq, off);
        if ((d & 31) == 0) wsum[d >> 5] = sq;
        __syncthreads();
        float tot = wsum[0] + wsum[1] + wsum[2] + wsum[3];
        y *= rsqrtf(tot * (1.0f / 128.0f) + 1.1920929e-7f);
    }

    dst[((size_t)(b * nh + h) * Sc + s) * Dc + d] = y;
}

// ---------------------------------------------------------------------------
// Flash attention, fp32, causal, GQA (H=16 query heads over HKV=4 kv heads).
// q,k,v in [B,heads,S,D]; output written to [B,S,H*D].
// BM=BN=64, 256 threads: 4x4 score microtile (rows ty+16i, cols tx+16j),
// 4x8 output microtile (cols tx*8..tx*8+7). Online softmax per row via
// shfl reductions across the 16-lane tx group.
// ---------------------------------------------------------------------------
#define FBM 64
#define FBN 64
#define SQ_ELEMS (128 * 65)
#define SK_ELEMS (128 * 65)
#define SV_ELEMS (64 * 128)
#define SS_ELEMS (64 * 65)
#define SMEM_FLASH ((SQ_ELEMS + SK_ELEMS + SV_ELEMS + SS_ELEMS) * sizeof(float))

__global__ __launch_bounds__(256)
void flash_attn(const float* __restrict__ q, const float* __restrict__ k,
                const float* __restrict__ v, float* __restrict__ o) {
    extern __shared__ float sm[];
    float* sq = sm;                      // [128][65]  Q transposed (d-major)
    float* sk = sq + SQ_ELEMS;           // [128][65]  K transposed (d-major)
    float* sv = sk + SK_ELEMS;           // [64][128]  V natural
    float* ss = sv + SV_ELEMS;           // [64][65]   P (exp scores)

    const int bh = blockIdx.y;
    const int b  = bh / Hc;
    const int h  = bh % Hc;
    const int hk = h / (Hc / HKVc);
    const int i0 = blockIdx.x * FBM;

    const int tid  = threadIdx.x;
    const int tx   = tid & 15;
    const int ty   = tid >> 4;
    const int lane = tid & 31;
    const int wrp  = tid >> 5;

    const float* qg = q + ((size_t)(b * Hc   + h ) * Sc + i0) * Dc;
    const float* kg = k + ((size_t)(b * HKVc + hk) * Sc) * Dc;
    const float* vg = v + ((size_t)(b * HKVc + hk) * Sc) * Dc;

    // Load Q tile transposed into smem (once).
    for (int r = wrp; r < FBM; r += 8) {
        float4 t = *(const float4*)(qg + (size_t)r * Dc + lane * 4);
        sq[(lane * 4 + 0) * 65 + r] = t.x;
        sq[(lane * 4 + 1) * 65 + r] = t.y;
        sq[(lane * 4 + 2) * 65 + r] = t.z;
        sq[(lane * 4 + 3) * 65 + r] = t.w;
    }

    float mrow[4], lrow[4], outv[4][8];
#pragma unroll
    for (int i = 0; i < 4; i++) {
        mrow[i] = -1e30f;
        lrow[i] = 0.0f;
#pragma unroll
        for (int c = 0; c < 8; c++) outv[i][c] = 0.0f;
    }
    const float scale = 0.08838834764831845f;  // 1/sqrt(128)

    for (int j0 = 0; j0 <= i0; j0 += FBN) {
        __syncthreads();  // protect sk/sv/ss from previous iteration readers
        // Load K (transposed) and V (natural) tiles.
        for (int r = wrp; r < FBN; r += 8) {
            float4 t = *(const float4*)(kg + (size_t)(j0 + r) * Dc + lane * 4);
            sk[(lane * 4 + 0) * 65 + r] = t.x;
            sk[(lane * 4 + 1) * 65 + r] = t.y;
            sk[(lane * 4 + 2) * 65 + r] = t.z;
            sk[(lane * 4 + 3) * 65 + r] = t.w;
            float4 u = *(const float4*)(vg + (size_t)(j0 + r) * Dc + lane * 4);
            *(float4*)(sv + r * Dc + lane * 4) = u;
        }
        __syncthreads();

        // S = Q @ K^T (4x4 per thread)
        float acc[4][4] = {};
#pragma unroll 4
        for (int d = 0; d < Dc; d++) {
            float qf[4], kf[4];
#pragma unroll
            for (int i = 0; i < 4; i++) qf[i] = sq[d * 65 + ty + 16 * i];
#pragma unroll
            for (int j = 0; j < 4; j++) kf[j] = sk[d * 65 + tx + 16 * j];
#pragma unroll
            for (int i = 0; i < 4; i++)
#pragma unroll
                for (int j = 0; j < 4; j++)
                    acc[i][j] += qf[i] * kf[j];
        }

        // Online softmax, per row (rows ty+16i; stats reduced across tx group)
#pragma unroll
        for (int i = 0; i < 4; i++) {
            const int gm = i0 + ty + 16 * i;
            float sij[4];
            float tmax = -1e30f;
#pragma unroll
            for (int j = 0; j < 4; j++) {
                const int gn = j0 + tx + 16 * j;
                float sval = acc[i][j] * scale;
                if (gn > gm) sval = -1e30f;   // causal mask
                sij[j] = sval;
                tmax = fmaxf(tmax, sval);
            }
#pragma unroll
            for (int off = 8; off; off >>= 1)
                tmax = fmaxf(tmax, __shfl_xor_sync(0xffffffffu, tmax, off));
            const float mnew = fmaxf(mrow[i], tmax);
            float ps = 0.0f;
#pragma unroll
            for (int j = 0; j < 4; j++) {
                float p = __expf(sij[j] - mnew);
                ps += p;
                ss[(ty + 16 * i) * 65 + tx + 16 * j] = p;
            }
#pragma unroll
            for (int off = 8; off; off >>= 1)
                ps += __shfl_xor_sync(0xffffffffu, ps, off);
            const float fac = __expf(mrow[i] - mnew);
            lrow[i] = lrow[i] * fac + ps;
            mrow[i] = mnew;
#pragma unroll
            for (int c = 0; c < 8; c++) outv[i][c] *= fac;
        }
        __syncthreads();

        // O += P @ V
        for (int n = 0; n < FBN; n++) {
            float4 v0 = *(const float4*)(sv + n * Dc + tx * 8);
            float4 v1 = *(const float4*)(sv + n * Dc + tx * 8 + 4);
#pragma unroll
            for (int i = 0; i < 4; i++) {
                const float p = ss[(ty + 16 * i) * 65 + n];
                outv[i][0] += p * v0.x;
                outv[i][1] += p * v0.y;
                outv[i][2] += p * v0.z;
                outv[i][3] += p * v0.w;
                outv[i][4] += p * v1.x;
                outv[i][5] += p * v1.y;
                outv[i][6] += p * v1.z;
                outv[i][7] += p * v1.w;
            }
        }
    }

    // Normalize and write [B,S,H*D]
#pragma unroll
    for (int i = 0; i < 4; i++) {
        const int gi = i0 + ty + 16 * i;
        const float inv = 1.0f / lrow[i];
        float* op = o + (size_t)(b * Sc + gi) * HIDc + h * Dc + tx * 8;
        float4 r0 = make_float4(outv[i][0] * inv, outv[i][1] * inv,
                                outv[i][2] * inv, outv[i][3] * inv);
        float4 r1 = make_float4(outv[i][4] * inv, outv[i][5] * inv,
                                outv[i][6] * inv, outv[i][7] * inv);
        *(float4*)op       = r0;
        *(float4*)(op + 4) = r1;
    }
}

// ---------------------------------------------------------------------------
// kernel_launch
// inputs: x, cos, sin, Wq, Wk, Wv, Wo   (all float32)
// ---------------------------------------------------------------------------
extern "C" void kernel_launch(void* const* d_in, const int* in_sizes, int n_in,
                              void* d_out, int out_size) {
    (void)in_sizes; (void)n_in; (void)out_size;
    const float* x    = (const float*)d_in[0];
    const float* cosp = (const float*)d_in[1];
    const float* sinp = (const float*)d_in[2];
    const float* Wq   = (const float*)d_in[3];
    const float* Wk   = (const float*)d_in[4];
    const float* Wv   = (const float*)d_in[5];
    const float* Wo   = (const float*)d_in[6];
    float* out = (float*)d_out;

    float *q, *k, *v, *qt, *kt, *vt, *ao;
    cudaGetSymbolAddress((void**)&q,  g_q);
    cudaGetSymbolAddress((void**)&k,  g_k);
    cudaGetSymbolAddress((void**)&v,  g_v);
    cudaGetSymbolAddress((void**)&qt, g_qt);
    cudaGetSymbolAddress((void**)&kt, g_kt);
    cudaGetSymbolAddress((void**)&vt, g_vt);
    cudaGetSymbolAddress((void**)&ao, g_ao);

    const int M = Bc * Sc;  // 4096

    // QKV projections
    sgemm_nt<<<dim3((Hc * Dc) / 128,   M / 128), 256>>>(x, Wq, q, M, Hc * Dc,   HIDc);
    sgemm_nt<<<dim3((HKVc * Dc) / 128, M / 128), 256>>>(x, Wk, k, M, HKVc * Dc, HIDc);
    sgemm_nt<<<dim3((HKVc * Dc) / 128, M / 128), 256>>>(x, Wv, v, M, HKVc * Dc, HIDc);

    // RoPE + RMSNorm + transpose (V: transpose only)
    rope_rms_transpose<<<Bc * Sc * Hc,   128>>>(q, qt, cosp, sinp, Hc,   1);
    rope_rms_transpose<<<Bc * Sc * HKVc, 128>>>(k, kt, cosp, sinp, HKVc, 1);
    rope_rms_transpose<<<Bc * Sc * HKVc, 128>>>(v, vt, cosp, sinp, HKVc, 0);

    // Flash attention (causal, GQA)
    cudaFuncSetAttribute(flash_attn, cudaFuncAttributeMaxDynamicSharedMemorySize,
                         (int)SMEM_FLASH);
    flash_attn<<<dim3(Sc / FBM, Bc * Hc), 256, SMEM_FLASH>>>(qt, kt, vt, ao);

    // Output projection -> d_out
    sgemm_nt<<<dim3(HIDc / 128, M / 128), 256>>>(ao, Wo, out, M, HIDc, HIDc);
}

// round 16
// speedup vs baseline: 1.0010x; 1.0010x over previous
#include <cuda_runtime.h>
#include <math.h>

// Problem constants
#define Bc   2
#define Sc   2048
#define HIDc 2048
#define Hc   16
#define HKVc 4
#define Dc   128

// ---------------------------------------------------------------------------
// Scratch (device globals; no dynamic allocation allowed)
// ---------------------------------------------------------------------------
__device__ float g_q [(size_t)Bc * Sc * Hc   * Dc];   // [B,S,H*D]   raw Q proj
__device__ float g_k [(size_t)Bc * Sc * HKVc * Dc];   // [B,S,HKV*D] raw K proj
__device__ float g_v [(size_t)Bc * Sc * HKVc * Dc];   // [B,S,HKV*D] raw V proj
__device__ float g_qt[(size_t)Bc * Sc * Hc   * Dc];   // [B,H,S,D]   rope+rms Q
__device__ float g_kt[(size_t)Bc * Sc * HKVc * Dc];   // [B,HKV,S,D] rope+rms K
__device__ float g_vt[(size_t)Bc * Sc * HKVc * Dc];   // [B,HKV,S,D] V transposed
__device__ float g_ao[(size_t)Bc * Sc * Hc   * Dc];   // [B,S,H*D]   attn output

// ---------------------------------------------------------------------------
// SGEMM: C[M,N] = A[M,K] @ W[N,K]^T   (all row-major, dims multiples of 128/8)
// 128x128 block tile, 8-deep K, 8x8 per thread, 256 threads.
// ---------------------------------------------------------------------------
__global__ __launch_bounds__(256)
void sgemm_nt(const float* __restrict__ A, const float* __restrict__ W,
              float* __restrict__ C, int M, int N, int K) {
    __shared__ float As[8][128];
    __shared__ float Bs[8][128];

    const int tid = threadIdx.x;
    const int m0  = blockIdx.y * 128;
    const int n0  = blockIdx.x * 128;
    const int tx  = tid & 15;         // 0..15 -> 8 output cols each
    const int ty  = tid >> 4;         // 0..15 -> 8 output rows each
    const int lrow = tid >> 1;        // 0..127 (load row within tile)
    const int lcol = (tid & 1) << 2;  // 0 or 4  (load col within K-slab)

    const float* Ap = A + (size_t)(m0 + lrow) * K + lcol;
    const float* Wp = W + (size_t)(n0 + lrow) * K + lcol;

    float acc[8][8];
#pragma unroll
    for (int i = 0; i < 8; i++)
#pragma unroll
        for (int j = 0; j < 8; j++) acc[i][j] = 0.0f;

    for (int k0 = 0; k0 < K; k0 += 8) {
        float4 av = *(const float4*)(Ap + k0);
        float4 wv = *(const float4*)(Wp + k0);
        __syncthreads();
        As[lcol + 0][lrow] = av.x;
        As[lcol + 1][lrow] = av.y;
        As[lcol + 2][lrow] = av.z;
        As[lcol + 3][lrow] = av.w;
        Bs[lcol + 0][lrow] = wv.x;
        Bs[lcol + 1][lrow] = wv.y;
        Bs[lcol + 2][lrow] = wv.z;
        Bs[lcol + 3][lrow] = wv.w;
        __syncthreads();
#pragma unroll
        for (int kk = 0; kk < 8; kk++) {
            float a[8], b[8];
            *(float4*)&a[0] = *(const float4*)&As[kk][ty * 8];
            *(float4*)&a[4] = *(const float4*)&As[kk][ty * 8 + 4];
            *(float4*)&b[0] = *(const float4*)&Bs[kk][tx * 8];
            *(float4*)&b[4] = *(const float4*)&Bs[kk][tx * 8 + 4];
#pragma unroll
            for (int i = 0; i < 8; i++)
#pragma unroll
                for (int j = 0; j < 8; j++)
                    acc[i][j] += a[i] * b[j];
        }
    }

#pragma unroll
    for (int i = 0; i < 8; i++) {
        float* Cp = C + (size_t)(m0 + ty * 8 + i) * N + n0 + tx * 8;
        float4 c0 = make_float4(acc[i][0], acc[i][1], acc[i][2], acc[i][3]);
        float4 c1 = make_float4(acc[i][4], acc[i][5], acc[i][6], acc[i][7]);
        *(float4*)Cp       = c0;
        *(float4*)(Cp + 4) = c1;
    }
}

// ---------------------------------------------------------------------------
// RoPE + RMSNorm + transpose: src [B,S,nh*D] -> dst [B,nh,S,D]
// One block (128 threads) per (b,s,h). apply=0 -> plain transpose (for V).
// ---------------------------------------------------------------------------
__global__ __launch_bounds__(128)
void rope_rms_transpose(const float* __restrict__ src, float* __restrict__ dst,
                        const float* __restrict__ cosp, const float* __restrict__ sinp,
                        int nh, int apply) {
    const int idx = blockIdx.x;
    const int h = idx % nh;
    const int s = (idx / nh) % Sc;
    const int b = idx / (nh * Sc);
    const int d = threadIdx.x;

    float val = src[((size_t)(b * Sc + s) * nh + h) * Dc + d];
    float y = val;

    if (apply) {
        __shared__ float buf[Dc];
        __shared__ float wsum[4];
        buf[d] = val;
        __syncthreads();
        if (d < 64) {
            float c  = cosp[s * 64 + d];
            float sn = sinp[s * 64 + d];
            y = buf[d] * c + buf[d + 64] * sn;
        } else {
            float c  = cosp[s * 64 + d - 64];
            float sn = sinp[s * 64 + d - 64];
            y = -buf[d - 64] * sn + buf[d] * c;
        }
        float sq = y * y;
#pragma unroll
        for (int off = 16; off; off >>= 1)
            sq += __shfl_xor_sync(0xffffffffu, sq, off);
        if ((d & 31) == 0) wsum[d >> 5] = sq;
        __syncthreads();
        float tot = wsum[0] + wsum[1] + wsum[2] + wsum[3];
        y *= rsqrtf(tot * (1.0f / 128.0f) + 1.1920929e-7f);
    }

    dst[((size_t)(b * nh + h) * Sc + s) * Dc + d] = y;
}

// ---------------------------------------------------------------------------
// Flash attention, fp32, causal, GQA (H=16 query heads over HKV=4 kv heads).
// q,k,v in [B,heads,S,D]; output written to [B,S,H*D].
// BM=BN=64, 256 threads: 4x4 score microtile (rows ty+16i, cols tx+16j),
// 4x8 output microtile (cols tx*8..tx*8+7). Online softmax per row via
// shfl reductions across the 16-lane tx group.
// ---------------------------------------------------------------------------
#define FBM 64
#define FBN 64
#define SQ_ELEMS (128 * 65)
#define SK_ELEMS (128 * 65)
#define SV_ELEMS (64 * 128)
#define SS_ELEMS (64 * 65)
#define SMEM_FLASH ((SQ_ELEMS + SK_ELEMS + SV_ELEMS + SS_ELEMS) * sizeof(float))

__global__ __launch_bounds__(256)
void flash_attn(const float* __restrict__ q, const float* __restrict__ k,
                const float* __restrict__ v, float* __restrict__ o) {
    extern __shared__ float sm[];
    float* sq = sm;                      // [128][65]  Q transposed (d-major)
    float* sk = sq + SQ_ELEMS;           // [128][65]  K transposed (d-major)
    float* sv = sk + SK_ELEMS;           // [64][128]  V natural
    float* ss = sv + SV_ELEMS;           // [64][65]   P (exp scores)

    const int bh = blockIdx.y;
    const int b  = bh / Hc;
    const int h  = bh % Hc;
    const int hk = h / (Hc / HKVc);
    const int i0 = blockIdx.x * FBM;

    const int tid  = threadIdx.x;
    const int tx   = tid & 15;
    const int ty   = tid >> 4;
    const int lane = tid & 31;
    const int wrp  = tid >> 5;

    const float* qg = q + ((size_t)(b * Hc   + h ) * Sc + i0) * Dc;
    const float* kg = k + ((size_t)(b * HKVc + hk) * Sc) * Dc;
    const float* vg = v + ((size_t)(b * HKVc + hk) * Sc) * Dc;

    // Load Q tile transposed into smem (once).
    for (int r = wrp; r < FBM; r += 8) {
        float4 t = *(const float4*)(qg + (size_t)r * Dc + lane * 4);
        sq[(lane * 4 + 0) * 65 + r] = t.x;
        sq[(lane * 4 + 1) * 65 + r] = t.y;
        sq[(lane * 4 + 2) * 65 + r] = t.z;
        sq[(lane * 4 + 3) * 65 + r] = t.w;
    }

    float mrow[4], lrow[4], outv[4][8];
#pragma unroll
    for (int i = 0; i < 4; i++) {
        mrow[i] = -1e30f;
        lrow[i] = 0.0f;
#pragma unroll
        for (int c = 0; c < 8; c++) outv[i][c] = 0.0f;
    }
    const float scale = 0.08838834764831845f;  // 1/sqrt(128)

    for (int j0 = 0; j0 <= i0; j0 += FBN) {
        __syncthreads();  // protect sk/sv/ss from previous iteration readers
        // Load K (transposed) and V (natural) tiles.
        for (int r = wrp; r < FBN; r += 8) {
            float4 t = *(const float4*)(kg + (size_t)(j0 + r) * Dc + lane * 4);
            sk[(lane * 4 + 0) * 65 + r] = t.x;
            sk[(lane * 4 + 1) * 65 + r] = t.y;
            sk[(lane * 4 + 2) * 65 + r] = t.z;
            sk[(lane * 4 + 3) * 65 + r] = t.w;
            float4 u = *(const float4*)(vg + (size_t)(j0 + r) * Dc + lane * 4);
            *(float4*)(sv + r * Dc + lane * 4) = u;
        }
        __syncthreads();

        // S = Q @ K^T (4x4 per thread)
        float acc[4][4] = {};
#pragma unroll 4
        for (int d = 0; d < Dc; d++) {
            float qf[4], kf[4];
#pragma unroll
            for (int i = 0; i < 4; i++) qf[i] = sq[d * 65 + ty + 16 * i];
#pragma unroll
            for (int j = 0; j < 4; j++) kf[j] = sk[d * 65 + tx + 16 * j];
#pragma unroll
            for (int i = 0; i < 4; i++)
#pragma unroll
                for (int j = 0; j < 4; j++)
                    acc[i][j] += qf[i] * kf[j];
        }

        // Online softmax, per row (rows ty+16i; stats reduced across tx group)
#pragma unroll
        for (int i = 0; i < 4; i++) {
            const int gm = i0 + ty + 16 * i;
            float sij[4];
            float tmax = -1e30f;
#pragma unroll
            for (int j = 0; j < 4; j++) {
                const int gn = j0 + tx + 16 * j;
                float sval = acc[i][j] * scale;
                if (gn > gm) sval = -1e30f;   // causal mask
                sij[j] = sval;
                tmax = fmaxf(tmax, sval);
            }
#pragma unroll
            for (int off = 8; off; off >>= 1)
                tmax = fmaxf(tmax, __shfl_xor_sync(0xffffffffu, tmax, off));
            const float mnew = fmaxf(mrow[i], tmax);
            float ps = 0.0f;
#pragma unroll
            for (int j = 0; j < 4; j++) {
                float p = __expf(sij[j] - mnew);
                ps += p;
                ss[(ty + 16 * i) * 65 + tx + 16 * j] = p;
            }
#pragma unroll
            for (int off = 8; off; off >>= 1)
                ps += __shfl_xor_sync(0xffffffffu, ps, off);
            const float fac = __expf(mrow[i] - mnew);
            lrow[i] = lrow[i] * fac + ps;
            mrow[i] = mnew;
#pragma unroll
            for (int c = 0; c < 8; c++) outv[i][c] *= fac;
        }
        __syncthreads();

        // O += P @ V
        for (int n = 0; n < FBN; n++) {
            float4 v0 = *(const float4*)(sv + n * Dc + tx * 8);
            float4 v1 = *(const float4*)(sv + n * Dc + tx * 8 + 4);
#pragma unroll
            for (int i = 0; i < 4; i++) {
                const float p = ss[(ty + 16 * i) * 65 + n];
                outv[i][0] += p * v0.x;
                outv[i][1] += p * v0.y;
                outv[i][2] += p * v0.z;
                outv[i][3] += p * v0.w;
                outv[i][4] += p * v1.x;
                outv[i][5] += p * v1.y;
                outv[i][6] += p * v1.z;
                outv[i][7] += p * v1.w;
            }
        }
    }

    // Normalize and write [B,S,H*D]
#pragma unroll
    for (int i = 0; i < 4; i++) {
        const int gi = i0 + ty + 16 * i;
        const float inv = 1.0f / lrow[i];
        float* op = o + (size_t)(b * Sc + gi) * HIDc + h * Dc + tx * 8;
        float4 r0 = make_float4(outv[i][0] * inv, outv[i][1] * inv,
                                outv[i][2] * inv, outv[i][3] * inv);
        float4 r1 = make_float4(outv[i][4] * inv, outv[i][5] * inv,
                                outv[i][6] * inv, outv[i][7] * inv);
        *(float4*)op       = r0;
        *(float4*)(op + 4) = r1;
    }
}

// ---------------------------------------------------------------------------
// kernel_launch
// inputs: x, cos, sin, Wq, Wk, Wv, Wo   (all float32)
// ---------------------------------------------------------------------------
extern "C" void kernel_launch(void* const* d_in, const int* in_sizes, int n_in,
                              void* d_out, int out_size) {
    (void)in_sizes; (void)n_in; (void)out_size;
    const float* x    = (const float*)d_in[0];
    const float* cosp = (const float*)d_in[1];
    const float* sinp = (const float*)d_in[2];
    const float* Wq   = (const float*)d_in[3];
    const float* Wk   = (const float*)d_in[4];
    const float* Wv   = (const float*)d_in[5];
    const float* Wo   = (const float*)d_in[6];
    float* out = (float*)d_out;

    float *q, *k, *v, *qt, *kt, *vt, *ao;
    cudaGetSymbolAddress((void**)&q,  g_q);
    cudaGetSymbolAddress((void**)&k,  g_k);
    cudaGetSymbolAddress((void**)&v,  g_v);
    cudaGetSymbolAddress((void**)&qt, g_qt);
    cudaGetSymbolAddress((void**)&kt, g_kt);
    cudaGetSymbolAddress((void**)&vt, g_vt);
    cudaGetSymbolAddress((void**)&ao, g_ao);

    const int M = Bc * Sc;  // 4096

    // QKV projections
    sgemm_nt<<<dim3((Hc * Dc) / 128,   M / 128), 256>>>(x, Wq, q, M, Hc * Dc,   HIDc);
    sgemm_nt<<<dim3((HKVc * Dc) / 128, M / 128), 256>>>(x, Wk, k, M, HKVc * Dc, HIDc);
    sgemm_nt<<<dim3((HKVc * Dc) / 128, M / 128), 256>>>(x, Wv, v, M, HKVc * Dc, HIDc);

    // RoPE + RMSNorm + transpose (V: transpose only)
    rope_rms_transpose<<<Bc * Sc * Hc,   128>>>(q, qt, cosp, sinp, Hc,   1);
    rope_rms_transpose<<<Bc * Sc * HKVc, 128>>>(k, kt, cosp, sinp, HKVc, 1);
    rope_rms_transpose<<<Bc * Sc * HKVc, 128>>>(v, vt, cosp, sinp, HKVc, 0);

    // Flash attention (causal, GQA)
    cudaFuncSetAttribute(flash_attn, cudaFuncAttributeMaxDynamicSharedMemorySize,
                         (int)SMEM_FLASH);
    flash_attn<<<dim3(Sc / FBM, Bc * Hc), 256, SMEM_FLASH>>>(qt, kt, vt, ao);

    // Output projection -> d_out
    sgemm_nt<<<dim3(HIDc / 128, M / 128), 256>>>(ao, Wo, out, M, HIDc, HIDc);
}